// round 16
// baseline (speedup 1.0000x reference)
#include <cuda_runtime.h>
#include <cuda_fp16.h>
#include <cstdint>
#include <math.h>

// Problem dims
#define BB   512
#define TT   512
#define IN0  16
#define HH   256
#define NG   1024          // 4*H
#define IN1  (2 * HH)      // 512
#define LOUT 64

// ---------------- device scratch (static, no allocations) ----------------
__device__ __half g_gx1 [(size_t)2 * TT * BB * NG];  // layer-1 input-GEMM precompute (+bias), fp16
__device__ __half g_x1h[(size_t)BB * TT * IN1];      // fp16 x1 (layer-0 output)
__device__ __half g_w1 [2][NG][IN1];                 // fp16 w_ih1
__device__ __half g_x0h[(size_t)BB * TT * IN0];      // fp16 x
__device__ __half g_w0 [2][NG][IN0];                 // fp16 w_ih0
__device__ __half g_whh[2][2][NG][HH];               // fp16 [layer][dir]
__device__ __half g_hh[2][2][2][BB][HH];             // [layer][parity][dir][b][j]
__device__ unsigned g_garr[2][32];
__device__ unsigned g_ggen[2][32];

__global__ void zero_kernel()
{
    int tid = blockIdx.x * blockDim.x + threadIdx.x;
    int stride = gridDim.x * blockDim.x;
    const int nh = 2 * 2 * 2 * BB * HH / 2;   // uint count
    for (int i = tid; i < nh; i += stride)
        ((unsigned*)g_hh)[i] = 0u;
    if (tid < 64) {
        ((unsigned*)g_garr)[tid] = 0u;
        ((unsigned*)g_ggen)[tid] = 0u;
    }
}

__device__ __forceinline__ float sigf(float x) { return 1.f / (1.f + __expf(-x)); }
__device__ __forceinline__ float tanhf_fast(float x) { return 2.f / (1.f + __expf(-2.f * x)) - 1.f; }

// ======================= helpers =======================
__device__ __forceinline__ uint32_t smem_u32(const void* p) {
    uint32_t a;
    asm("{ .reg .u64 t; cvta.to.shared.u64 t, %1; cvt.u32.u64 %0, t; }" : "=r"(a) : "l"(p));
    return a;
}
#define CP_ASYNC16(dst, src) \
    asm volatile("cp.async.cg.shared.global [%0], [%1], 16;" :: "r"(dst), "l"(src) : "memory")
#define CP_COMMIT() asm volatile("cp.async.commit_group;" ::: "memory")
#define CP_WAIT1()  asm volatile("cp.async.wait_group 1;" ::: "memory")
#define CP_WAIT0()  asm volatile("cp.async.wait_group 0;" ::: "memory")
#define LDMATRIX_X4(r0, r1, r2, r3, addr) \
    asm volatile("ldmatrix.sync.aligned.m8n8.x4.shared.b16 {%0,%1,%2,%3}, [%4];" \
                 : "=r"(r0), "=r"(r1), "=r"(r2), "=r"(r3) : "r"(addr))
#define MMA_F16(c0, c1, c2, c3, a0, a1, a2, a3, b0, b1) \
    asm volatile("mma.sync.aligned.m16n8k16.row.col.f32.f16.f16.f32 " \
                 "{%0,%1,%2,%3}, {%4,%5,%6,%7}, {%8,%9}, {%0,%1,%2,%3};" \
                 : "+f"(c0), "+f"(c1), "+f"(c2), "+f"(c3) \
                 : "r"(a0), "r"(a1), "r"(a2), "r"(a3), "r"(b0), "r"(b1))

// ---------------- per-group (8-block) barrier ----------------
__device__ __forceinline__ void group_sync(unsigned* arr, unsigned* gen)
{
    __syncthreads();
    if (threadIdx.x == 0) {
        __threadfence();
        unsigned g = *(volatile unsigned*)gen;
        if (atomicAdd(arr, 1u) == 7u) {
            atomicExch(arr, 0u);
            __threadfence();
            atomicAdd(gen, 1u);
        } else {
            while (*(volatile unsigned*)gen == g) { __nanosleep(32); }
        }
    }
    __syncthreads();
}

// ======================= conversion kernel =======================
__global__ void convh_kernel(const float* __restrict__ src, __half* __restrict__ dst, int n)
{
    int i = blockIdx.x * blockDim.x + threadIdx.x;
    int stride = gridDim.x * blockDim.x;
    for (; i < n; i += stride)
        dst[i] = __float2half_rn(src[i]);
}

// ======================= tensorized persistent LSTM layer =======================
// 256 blocks: 16 m-tiles (32 rows) x 8 n-tiles (32 h-cols x 4 gates) x 2 dirs,
// __launch_bounds__(256,2): co-resident. Single-pass fp16 MMA; W rows gate-
// interleaved -> cell update fully in registers. gx1 read as fp16 (this round).
template<int KIN>
__global__ void __launch_bounds__(256, 2) lstm_seq_tc(
    const float* __restrict__ bias_f, const float* __restrict__ bias_b)
{
    constexpr int LAYER = (KIN == 16) ? 0 : 1;
    constexpr int K     = KIN + HH;          // 272 / 256
    constexpr int KS    = K / 16;            // 17 / 16
    constexpr int SEGW  = K / 8;             // 34 / 32
    constexpr int XSEG  = KIN / 8;           // 2 / 0
    constexpr int ROWB  = (K + 8) * 2;       // 560 / 528

    extern __shared__ char smem[];
    const uint32_t sA  = smem_u32(smem);
    const uint32_t sW  = sA + 32 * ROWB;
    const uint32_t sGx = sA + 160 * ROWB;    // layer 1 only: 32 rows x 128 fp16 (8KB)
    __half* GxS = (__half*)(smem + 160 * ROWB);
    __shared__ float bias_s[128];

    const int tid = threadIdx.x;
    const int wid = tid >> 5, lid = tid & 31;
    const int warp_m = wid >> 2, warp_n = wid & 3;   // warp_m 0..1 (16 rows each)
    const int bx = blockIdx.x;
    const int n_idx = bx & 7, m_idx = (bx >> 3) & 15, dir = bx >> 7;
    const int n0 = n_idx * 32, m0 = m_idx * 32;
    unsigned* barr = &g_garr[LAYER][dir * 16 + m_idx];
    unsigned* bgen = &g_ggen[LAYER][dir * 16 + m_idx];

    if (LAYER == 0 && tid < 128)
        bias_s[tid] = (dir ? bias_b : bias_f)[(tid >> 5) * 256 + n0 + (tid & 31)];

    // ---- preload W tile: row r -> gate=(r>>3)&3, hcol=(r>>5)*8+(r&7) ----
    {
        const __half* wh = &g_whh[LAYER][dir][0][0];
        for (int s = tid; s < 128 * SEGW; s += 256) {
            int r = s / SEGW, seg = s % SEGW;
            int n = ((r >> 3) & 3) * 256 + n0 + (r >> 5) * 8 + (r & 7);
            uint32_t dst = (uint32_t)(r * ROWB + seg * 16);
            if (KIN == 16 && seg < XSEG) {
                CP_ASYNC16(sW + dst, (const char*)&g_w0[dir][n][seg * 8]);
            } else {
                int hs = seg - XSEG;
                CP_ASYNC16(sW + dst, (const char*)&wh[n * HH + hs * 8]);
            }
        }
        CP_COMMIT(); CP_WAIT0();
        __syncthreads();
    }

    float cstate[4];
#pragma unroll
    for (int e = 0; e < 4; e++) cstate[e] = 0.f;

    const int a_row  = lid & 15;
    const int a_kof2 = (lid >> 4) * 16;
    const int b_g    = lid >> 3;
    const int b_row  = (b_g >> 1) * 8 + (lid & 7);
    const int b_kof2 = (b_g & 1) * 16;

    for (int t = 0; t < TT; t++) {
        const int tt  = dir ? (TT - 1 - t) : t;
        const int par = t & 1;
        const __half* hph = &g_hh[LAYER][par][dir][0][0];

        // ---- load A tile: [x_t(16) |] h_prev(256), 32 rows ----
        for (int s = tid; s < 32 * SEGW; s += 256) {
            int r = s / SEGW, seg = s % SEGW;
            int b = m0 + r;
            uint32_t dst = (uint32_t)(r * ROWB + seg * 16);
            if (KIN == 16 && seg < XSEG) {
                size_t xo = ((size_t)b * TT + tt) * IN0 + seg * 8;
                CP_ASYNC16(sA + dst, (const char*)(g_x0h + xo));
            } else {
                int hs = seg - XSEG;
                CP_ASYNC16(sA + dst, (const char*)&hph[b * HH + hs * 8]);
            }
        }
        CP_COMMIT();

        if (LAYER == 1) {
            // prefetch gx1 tile (32 rows x 4 gates x 32 cols fp16 = 8KB), overlap with MMA
            const __half* gxb = g_gx1 + (((size_t)dir * TT + tt) * BB + m0) * NG + n0;
#pragma unroll
            for (int i = 0; i < 2; i++) {
                int ch = tid + 256 * i;            // 0..511
                int row = ch >> 4;
                int sub = ch & 15;                 // gate(2b) x seg(2b)
                int gate = sub >> 2, seg = sub & 3;
                const char* src = (const char*)(gxb + (size_t)row * NG + gate * 256) + seg * 16;
                CP_ASYNC16(sGx + (uint32_t)(row * 256 + gate * 64 + seg * 16), src);
            }
            CP_COMMIT();
            CP_WAIT1();      // A-tile complete; gx still in flight
        } else {
            CP_WAIT0();
        }
        __syncthreads();

        float c[4][4];
#pragma unroll
        for (int nt = 0; nt < 4; nt++)
#pragma unroll
            for (int r = 0; r < 4; r++) c[nt][r] = 0.f;

#pragma unroll
        for (int ks = 0; ks < KS; ks++) {
            const int kb = ks * 32;
            uint32_t aH[4], bW[2][4];
            {
                uint32_t off = (uint32_t)((warp_m * 16 + a_row) * ROWB + kb + a_kof2);
                LDMATRIX_X4(aH[0], aH[1], aH[2], aH[3], sA + off);
            }
#pragma unroll
            for (int bt = 0; bt < 2; bt++) {
                uint32_t off = (uint32_t)((warp_n * 32 + bt * 16 + b_row) * ROWB + kb + b_kof2);
                LDMATRIX_X4(bW[bt][0], bW[bt][1], bW[bt][2], bW[bt][3], sW + off);
            }
#pragma unroll
            for (int nt = 0; nt < 4; nt++) {
                int bt = nt >> 1, sub = (nt & 1) * 2;
                MMA_F16(c[nt][0], c[nt][1], c[nt][2], c[nt][3],
                        aH[0], aH[1], aH[2], aH[3],
                        bW[bt][sub], bW[bt][sub + 1]);
            }
        }

        if (LAYER == 1) {
            CP_WAIT0();          // gx tile landed (overlapped with MMA)
            __syncthreads();     // make all threads' gx cp.asyncs visible
        }

        // ---- cell update entirely in registers: c[gate][r] ----
        __half* hnh = &g_hh[LAYER][par ^ 1][dir][0][0];
#pragma unroll
        for (int rh = 0; rh < 2; rh++) {
            int row  = warp_m * 16 + (lid >> 2) + rh * 8;
            int colp = warp_n * 8 + (lid & 3) * 2;     // even col in [0,32)
            int b = m0 + row;
            float hv[2];
#pragma unroll
            for (int cc = 0; cc < 2; cc++) {
                int r = rh * 2 + cc;
                int e = rh * 2 + cc;
                float gi = c[0][r];
                float gf = c[1][r];
                float gg = c[2][r];
                float go = c[3][r];
                if (LAYER == 0) {
                    gi += bias_s[colp + cc];
                    gf += bias_s[32 + colp + cc];
                    gg += bias_s[64 + colp + cc];
                    go += bias_s[96 + colp + cc];
                } else {
                    gi += __half2float(GxS[row * 128 + colp + cc]);
                    gf += __half2float(GxS[row * 128 + 32 + colp + cc]);
                    gg += __half2float(GxS[row * 128 + 64 + colp + cc]);
                    go += __half2float(GxS[row * 128 + 96 + colp + cc]);
                }
                float ccv = sigf(gf) * cstate[e] + sigf(gi) * tanhf_fast(gg);
                cstate[e] = ccv;
                hv[cc] = sigf(go) * tanhf_fast(ccv);
            }
            __half2 h2 = __floats2half2_rn(hv[0], hv[1]);
            *(__half2*)&hnh[(size_t)b * HH + n0 + colp] = h2;
            if (LAYER == 0)
                *(__half2*)&g_x1h[((size_t)b * TT + tt) * IN1 + dir * HH + n0 + colp] = h2;
        }
        group_sync(barr, bgen);
    }
}

// ======================= layer-1 input pre-GEMM: fp16 single-pass, occ 2 ======
#define PG_PAD    40
#define PG_HBYTES (128 * PG_PAD * 2)               // 10240 per plane
#define PG_STAGE  (2 * PG_HBYTES)                  // 20480 (Ah, Wh)
#define PG_SMEM   (2 * PG_STAGE)                   // 40960

__device__ __forceinline__ void pg_load_stage(
    uint32_t sbase, const __half* Ah, const __half* Wh, int k0, int tid)
{
#pragma unroll
    for (int i = 0; i < 2; i++) {
        int chunk = tid + 256 * i;
        int row = chunk >> 2, seg = chunk & 3;
        uint32_t doff = (uint32_t)(row * (PG_PAD * 2) + seg * 16);
        CP_ASYNC16(sbase + doff,             (const char*)(Ah + (size_t)row * IN1 + k0) + seg * 16);
        CP_ASYNC16(sbase + PG_HBYTES + doff, (const char*)(Wh + (size_t)row * IN1 + k0) + seg * 16);
    }
}

__global__ void __launch_bounds__(256, 2) pregemm_mma(
    const float* __restrict__ b1f, const float* __restrict__ b1b)
{
    extern __shared__ char smem[];
    __shared__ float bias_s[128];
    const uint32_t s0 = smem_u32(smem);
    const int tid = threadIdx.x;
    const int wid = tid >> 5, lid = tid & 31;
    const int warp_m = wid >> 2, warp_n = wid & 3;

    const int dir   = blockIdx.x >> 3;
    const int ntile = blockIdx.x & 7;
    const int mtile = blockIdx.y;

    const float* bsrc = dir ? b1b : b1f;
    if (tid < 128) bias_s[tid] = bsrc[ntile * 128 + tid];

    const __half* Ah = g_x1h + (size_t)mtile * 128 * IN1;
    const __half* Wh = &g_w1[dir][ntile * 128][0];

    float c[4][4][4];
#pragma unroll
    for (int mt = 0; mt < 4; mt++)
#pragma unroll
        for (int nt = 0; nt < 4; nt++)
#pragma unroll
            for (int r = 0; r < 4; r++) c[mt][nt][r] = 0.f;

    pg_load_stage(s0,            Ah, Wh, 0,  tid); CP_COMMIT();
    pg_load_stage(s0 + PG_STAGE, Ah, Wh, 32, tid); CP_COMMIT();

    const int a_row = (lid & 15);
    const int a_kof = (lid >> 4) * 8;
    const int b_g   = lid >> 3;
    const int b_row = (b_g >> 1) * 8 + (lid & 7);
    const int b_kof = (b_g & 1) * 8;

    for (int ci = 0; ci < 16; ci++) {
        if (ci == 15) CP_WAIT0(); else CP_WAIT1();
        __syncthreads();

        const uint32_t sb = s0 + (ci & 1) * PG_STAGE;
        const uint32_t sA = sb;
        const uint32_t sW = sb + PG_HBYTES;

#pragma unroll
        for (int ks = 0; ks < 32; ks += 16) {
            uint32_t aH[4][4], bW[2][4];
#pragma unroll
            for (int mt = 0; mt < 4; mt++) {
                int row = warp_m * 64 + mt * 16 + a_row;
                uint32_t off = (uint32_t)(row * (PG_PAD * 2) + (ks + a_kof) * 2);
                LDMATRIX_X4(aH[mt][0], aH[mt][1], aH[mt][2], aH[mt][3], sA + off);
            }
#pragma unroll
            for (int bt = 0; bt < 2; bt++) {
                int row = warp_n * 32 + bt * 16 + b_row;
                uint32_t off = (uint32_t)(row * (PG_PAD * 2) + (ks + b_kof) * 2);
                LDMATRIX_X4(bW[bt][0], bW[bt][1], bW[bt][2], bW[bt][3], sW + off);
            }
#pragma unroll
            for (int mt = 0; mt < 4; mt++)
#pragma unroll
                for (int nt = 0; nt < 4; nt++) {
                    int bt = nt >> 1, sub = (nt & 1) * 2;
                    MMA_F16(c[mt][nt][0], c[mt][nt][1], c[mt][nt][2], c[mt][nt][3],
                            aH[mt][0], aH[mt][1], aH[mt][2], aH[mt][3],
                            bW[bt][sub], bW[bt][sub + 1]);
                }
        }
        __syncthreads();
        if (ci + 2 < 16) {
            pg_load_stage(s0 + (ci & 1) * PG_STAGE, Ah, Wh, (ci + 2) * 32, tid);
            CP_COMMIT();
        }
    }

    // epilogue: +bias, convert to fp16, store __half2
#pragma unroll
    for (int mt = 0; mt < 4; mt++) {
#pragma unroll
        for (int rh = 0; rh < 2; rh++) {
            int row = warp_m * 64 + mt * 16 + (lid >> 2) + rh * 8;
            size_t R = (size_t)mtile * 128 + row;
            int b = (int)(R >> 9), t = (int)(R & 511);
            __half* dst = g_gx1 + (((size_t)dir * TT + t) * BB + b) * NG + ntile * 128;
#pragma unroll
            for (int nt = 0; nt < 4; nt++) {
                int col = warp_n * 32 + nt * 8 + (lid & 3) * 2;
                __half2 v = __floats2half2_rn(c[mt][nt][rh * 2 + 0] + bias_s[col],
                                              c[mt][nt][rh * 2 + 1] + bias_s[col + 1]);
                *(__half2*)(dst + col) = v;
            }
        }
    }
}

// ======================= final projection =======================
__global__ void fc_kernel(const float* __restrict__ fcw, const float* __restrict__ fcb,
                          float* __restrict__ out)
{
    int b = blockIdx.x;
    int l = threadIdx.x;   // 64 threads
    __shared__ float hs[2 * HH];
    for (int j = threadIdx.x; j < 2 * HH; j += blockDim.x) {
        int d = j >> 8, jj = j & 255;
        hs[j] = __half2float(g_hh[1][0][d][b][jj]);
    }
    __syncthreads();
    float s = fcb[l];
#pragma unroll 8
    for (int j = 0; j < 2 * HH; j++)
        s = fmaf(hs[j], fcw[l * (2 * HH) + j], s);
    out[b * LOUT + l] = s;
}

// ---------------- launch ----------------
extern "C" void kernel_launch(void* const* d_in, const int* in_sizes, int n_in,
                              void* d_out, int out_size)
{
    const float* x     = (const float*)d_in[0];
    const float* wih0f = (const float*)d_in[1];
    const float* whh0f = (const float*)d_in[2];
    const float* b0f   = (const float*)d_in[3];
    const float* wih0b = (const float*)d_in[4];
    const float* whh0b = (const float*)d_in[5];
    const float* b0b   = (const float*)d_in[6];
    const float* wih1f = (const float*)d_in[7];
    const float* whh1f = (const float*)d_in[8];
    const float* b1f   = (const float*)d_in[9];
    const float* wih1b = (const float*)d_in[10];
    const float* whh1b = (const float*)d_in[11];
    const float* b1b   = (const float*)d_in[12];
    const float* fcw   = (const float*)d_in[13];
    const float* fcb   = (const float*)d_in[14];
    float* out = (float*)d_out;

    const int SM0 = 160 * ((IN0 + HH + 8) * 2);              // 89600
    const int SM1 = 160 * ((HH + 8) * 2) + 32 * 128 * 2;     // 84480 + 8192 = 92672
    cudaFuncSetAttribute(lstm_seq_tc<16>, cudaFuncAttributeMaxDynamicSharedMemorySize, SM0);
    cudaFuncSetAttribute(lstm_seq_tc<0>,  cudaFuncAttributeMaxDynamicSharedMemorySize, SM1);
    cudaFuncSetAttribute(pregemm_mma, cudaFuncAttributeMaxDynamicSharedMemorySize, PG_SMEM);

    void *a_x0h, *a_w0, *a_whh, *a_w1;
    cudaGetSymbolAddress(&a_x0h, g_x0h);
    cudaGetSymbolAddress(&a_w0, g_w0);
    cudaGetSymbolAddress(&a_whh, g_whh);
    cudaGetSymbolAddress(&a_w1, g_w1);
    __half* p_x0h = (__half*)a_x0h;
    __half* p_w0  = (__half*)a_w0;
    __half* p_whh = (__half*)a_whh;
    __half* p_w1  = (__half*)a_w1;

    zero_kernel<<<128, 256>>>();
    convh_kernel<<<512, 256>>>(x, p_x0h, BB * TT * IN0);
    convh_kernel<<<32, 256>>>(wih0f, p_w0, NG * IN0);
    convh_kernel<<<32, 256>>>(wih0b, p_w0 + NG * IN0, NG * IN0);
    convh_kernel<<<256, 256>>>(whh0f, p_whh + 0 * NG * HH, NG * HH);
    convh_kernel<<<256, 256>>>(whh0b, p_whh + 1 * NG * HH, NG * HH);
    convh_kernel<<<256, 256>>>(whh1f, p_whh + 2 * NG * HH, NG * HH);
    convh_kernel<<<256, 256>>>(whh1b, p_whh + 3 * NG * HH, NG * HH);
    convh_kernel<<<512, 256>>>(wih1f, p_w1, NG * IN1);
    convh_kernel<<<512, 256>>>(wih1b, p_w1 + NG * IN1, NG * IN1);

    lstm_seq_tc<16><<<256, 256, SM0>>>(b0f, b0b);

    dim3 gt(16, 2048, 1);
    pregemm_mma<<<gt, 256, PG_SMEM>>>(b1f, b1b);

    lstm_seq_tc<0><<<256, 256, SM1>>>(nullptr, nullptr);

    fc_kernel<<<BB, LOUT>>>(fcw, fcb, out);
}

// round 17
// speedup vs baseline: 1.1434x; 1.1434x over previous
#include <cuda_runtime.h>
#include <cuda_fp16.h>
#include <cstdint>
#include <math.h>

// Problem dims
#define BB   512
#define TT   512
#define IN0  16
#define HH   256
#define NG   1024          // 4*H
#define IN1  (2 * HH)      // 512
#define LOUT 64

// ---------------- device scratch (static, no allocations) ----------------
__device__ float g_gx1 [(size_t)2 * TT * BB * NG];   // layer-1 input-GEMM precompute (+bias)
__device__ __half g_x1h[(size_t)BB * TT * IN1];      // fp16 x1 (layer-0 output)
__device__ __half g_w1 [2][NG][IN1];                 // fp16 w_ih1
__device__ __half g_x0h[(size_t)BB * TT * IN0];      // fp16 x
__device__ __half g_w0 [2][NG][IN0];                 // fp16 w_ih0
__device__ __half g_whh[2][2][NG][HH];               // fp16 [layer][dir]
__device__ __half g_hh[2][2][2][BB][HH];             // [layer][parity][dir][b][j]
__device__ unsigned g_garr[2][32];
__device__ unsigned g_ggen[2][32];

__global__ void zero_kernel()
{
    int tid = blockIdx.x * blockDim.x + threadIdx.x;
    int stride = gridDim.x * blockDim.x;
    const int nh = 2 * 2 * 2 * BB * HH / 2;   // uint count
    for (int i = tid; i < nh; i += stride)
        ((unsigned*)g_hh)[i] = 0u;
    if (tid < 64) {
        ((unsigned*)g_garr)[tid] = 0u;
        ((unsigned*)g_ggen)[tid] = 0u;
    }
}

// ---- hardware activations (MUFU.TANH, sm_75+) ----
__device__ __forceinline__ float tanh_hw(float x) {
    float y;
    asm("tanh.approx.f32 %0, %1;" : "=f"(y) : "f"(x));
    return y;
}
__device__ __forceinline__ float sig_hw(float x) {
    return fmaf(tanh_hw(0.5f * x), 0.5f, 0.5f);
}

// ======================= helpers =======================
__device__ __forceinline__ uint32_t smem_u32(const void* p) {
    uint32_t a;
    asm("{ .reg .u64 t; cvta.to.shared.u64 t, %1; cvt.u32.u64 %0, t; }" : "=r"(a) : "l"(p));
    return a;
}
#define CP_ASYNC16(dst, src) \
    asm volatile("cp.async.cg.shared.global [%0], [%1], 16;" :: "r"(dst), "l"(src) : "memory")
#define CP_COMMIT() asm volatile("cp.async.commit_group;" ::: "memory")
#define CP_WAIT1()  asm volatile("cp.async.wait_group 1;" ::: "memory")
#define CP_WAIT0()  asm volatile("cp.async.wait_group 0;" ::: "memory")
#define LDMATRIX_X4(r0, r1, r2, r3, addr) \
    asm volatile("ldmatrix.sync.aligned.m8n8.x4.shared.b16 {%0,%1,%2,%3}, [%4];" \
                 : "=r"(r0), "=r"(r1), "=r"(r2), "=r"(r3) : "r"(addr))
#define MMA_F16(c0, c1, c2, c3, a0, a1, a2, a3, b0, b1) \
    asm volatile("mma.sync.aligned.m16n8k16.row.col.f32.f16.f16.f32 " \
                 "{%0,%1,%2,%3}, {%4,%5,%6,%7}, {%8,%9}, {%0,%1,%2,%3};" \
                 : "+f"(c0), "+f"(c1), "+f"(c2), "+f"(c3) \
                 : "r"(a0), "r"(a1), "r"(a2), "r"(a3), "r"(b0), "r"(b1))

// ---------------- per-group (8-block) barrier: release-arrive / acquire-spin ----------------
// Release on the arrive covers this block's prior h STGs (L2 point of coherence);
// acquire pairs with the subsequent cp.async L2 reads (structure proven since R11).
__device__ __forceinline__ void group_sync(unsigned* arr, unsigned* gen)
{
    __syncthreads();
    if (threadIdx.x == 0) {
        unsigned g;
        asm volatile("ld.relaxed.gpu.u32 %0, [%1];" : "=r"(g) : "l"(gen) : "memory");
        unsigned a;
        asm volatile("atom.add.release.gpu.u32 %0, [%1], 1;" : "=r"(a) : "l"(arr) : "memory");
        if (a == 7u) {
            asm volatile("st.relaxed.gpu.u32 [%0], 0;" :: "l"(arr) : "memory");
            unsigned d;
            asm volatile("atom.add.release.gpu.u32 %0, [%1], 1;" : "=r"(d) : "l"(gen) : "memory");
        } else {
            unsigned cur;
            do {
                asm volatile("ld.acquire.gpu.u32 %0, [%1];" : "=r"(cur) : "l"(gen) : "memory");
            } while (cur == g);
        }
    }
    __syncthreads();
}

// ======================= conversion kernel =======================
__global__ void convh_kernel(const float* __restrict__ src, __half* __restrict__ dst, int n)
{
    int i = blockIdx.x * blockDim.x + threadIdx.x;
    int stride = gridDim.x * blockDim.x;
    for (; i < n; i += stride)
        dst[i] = __float2half_rn(src[i]);
}

// ======================= tensorized persistent LSTM layer =======================
// 256 blocks: 16 m-tiles (32 rows) x 8 n-tiles (32 h-cols x 4 gates) x 2 dirs,
// __launch_bounds__(256,2): co-resident. Single-pass fp16 MMA; W rows gate-
// interleaved -> cell update fully in registers. gx1 fp32 (R15-proven).
template<int KIN>
__global__ void __launch_bounds__(256, 2) lstm_seq_tc(
    const float* __restrict__ bias_f, const float* __restrict__ bias_b)
{
    constexpr int LAYER = (KIN == 16) ? 0 : 1;
    constexpr int K     = KIN + HH;          // 272 / 256
    constexpr int KS    = K / 16;            // 17 / 16
    constexpr int SEGW  = K / 8;             // 34 / 32
    constexpr int XSEG  = KIN / 8;           // 2 / 0
    constexpr int ROWB  = (K + 8) * 2;       // 560 / 528

    extern __shared__ char smem[];
    const uint32_t sA  = smem_u32(smem);
    const uint32_t sW  = sA + 32 * ROWB;
    const uint32_t sGx = sA + 160 * ROWB;    // layer 1 only: 32 rows x 128 fp32 (16KB)
    float* GxS = (float*)(smem + 160 * ROWB);

    const int tid = threadIdx.x;
    const int wid = tid >> 5, lid = tid & 31;
    const int warp_m = wid >> 2, warp_n = wid & 3;   // warp_m 0..1 (16 rows each)
    const int bx = blockIdx.x;
    const int n_idx = bx & 7, m_idx = (bx >> 3) & 15, dir = bx >> 7;
    const int n0 = n_idx * 32, m0 = m_idx * 32;
    unsigned* barr = &g_garr[LAYER][dir * 16 + m_idx];
    unsigned* bgen = &g_ggen[LAYER][dir * 16 + m_idx];

    const int colp = warp_n * 8 + (lid & 3) * 2;     // fixed even col in [0,32)

    // L0 bias: constant per thread for all 512 steps -> registers
    float breg[4][2];
    if (LAYER == 0) {
        const float* bias = dir ? bias_b : bias_f;
#pragma unroll
        for (int g = 0; g < 4; g++)
#pragma unroll
            for (int cc = 0; cc < 2; cc++)
                breg[g][cc] = bias[g * 256 + n0 + colp + cc];
    }

    // ---- preload W tile: row r -> gate=(r>>3)&3, hcol=(r>>5)*8+(r&7) ----
    {
        const __half* wh = &g_whh[LAYER][dir][0][0];
        for (int s = tid; s < 128 * SEGW; s += 256) {
            int r = s / SEGW, seg = s % SEGW;
            int n = ((r >> 3) & 3) * 256 + n0 + (r >> 5) * 8 + (r & 7);
            uint32_t dst = (uint32_t)(r * ROWB + seg * 16);
            if (KIN == 16 && seg < XSEG) {
                CP_ASYNC16(sW + dst, (const char*)&g_w0[dir][n][seg * 8]);
            } else {
                int hs = seg - XSEG;
                CP_ASYNC16(sW + dst, (const char*)&wh[n * HH + hs * 8]);
            }
        }
        CP_COMMIT(); CP_WAIT0();
        __syncthreads();
    }

    float cstate[4];
#pragma unroll
    for (int e = 0; e < 4; e++) cstate[e] = 0.f;

    const int a_row  = lid & 15;
    const int a_kof2 = (lid >> 4) * 16;
    const int b_g    = lid >> 3;
    const int b_row  = (b_g >> 1) * 8 + (lid & 7);
    const int b_kof2 = (b_g & 1) * 16;

    for (int t = 0; t < TT; t++) {
        const int tt  = dir ? (TT - 1 - t) : t;
        const int par = t & 1;
        const __half* hph = &g_hh[LAYER][par][dir][0][0];

        // ---- load A tile: [x_t(16) |] h_prev(256), 32 rows ----
        for (int s = tid; s < 32 * SEGW; s += 256) {
            int r = s / SEGW, seg = s % SEGW;
            int b = m0 + r;
            uint32_t dst = (uint32_t)(r * ROWB + seg * 16);
            if (KIN == 16 && seg < XSEG) {
                size_t xo = ((size_t)b * TT + tt) * IN0 + seg * 8;
                CP_ASYNC16(sA + dst, (const char*)(g_x0h + xo));
            } else {
                int hs = seg - XSEG;
                CP_ASYNC16(sA + dst, (const char*)&hph[b * HH + hs * 8]);
            }
        }
        CP_COMMIT();

        if (LAYER == 1) {
            // prefetch gx1 tile (32 rows x 4 gates x 32 cols fp32), overlapped with MMA
            const float* gxb = g_gx1 + (((size_t)dir * TT + tt) * BB + m0) * NG + n0;
#pragma unroll
            for (int i = 0; i < 4; i++) {
                int ch = tid + 256 * i;            // 0..1023
                int row = ch >> 5;
                int sub = ch & 31;
                int gate = sub >> 3, seg = sub & 7;
                const char* src = (const char*)(gxb + (size_t)row * NG + gate * 256) + seg * 16;
                CP_ASYNC16(sGx + (uint32_t)(row * 512 + gate * 128 + seg * 16), src);
            }
            CP_COMMIT();
            CP_WAIT1();      // A-tile complete; gx still in flight
        } else {
            CP_WAIT0();
        }
        __syncthreads();

        float c[4][4];
#pragma unroll
        for (int nt = 0; nt < 4; nt++)
#pragma unroll
            for (int r = 0; r < 4; r++) c[nt][r] = 0.f;

#pragma unroll
        for (int ks = 0; ks < KS; ks++) {
            const int kb = ks * 32;
            uint32_t aH[4], bW[2][4];
            {
                uint32_t off = (uint32_t)((warp_m * 16 + a_row) * ROWB + kb + a_kof2);
                LDMATRIX_X4(aH[0], aH[1], aH[2], aH[3], sA + off);
            }
#pragma unroll
            for (int bt = 0; bt < 2; bt++) {
                uint32_t off = (uint32_t)((warp_n * 32 + bt * 16 + b_row) * ROWB + kb + b_kof2);
                LDMATRIX_X4(bW[bt][0], bW[bt][1], bW[bt][2], bW[bt][3], sW + off);
            }
#pragma unroll
            for (int nt = 0; nt < 4; nt++) {
                int bt = nt >> 1, sub = (nt & 1) * 2;
                MMA_F16(c[nt][0], c[nt][1], c[nt][2], c[nt][3],
                        aH[0], aH[1], aH[2], aH[3],
                        bW[bt][sub], bW[bt][sub + 1]);
            }
        }

        if (LAYER == 1) {
            CP_WAIT0();          // gx tile landed (overlapped with MMA)
            __syncthreads();     // make all threads' gx cp.asyncs visible
        }

        // ---- cell update entirely in registers: c[gate][r] ----
        __half* hnh = &g_hh[LAYER][par ^ 1][dir][0][0];
#pragma unroll
        for (int rh = 0; rh < 2; rh++) {
            int row = warp_m * 16 + (lid >> 2) + rh * 8;
            int b = m0 + row;
            float hv[2];
#pragma unroll
            for (int cc = 0; cc < 2; cc++) {
                int r = rh * 2 + cc;
                int e = rh * 2 + cc;
                float gi = c[0][r];
                float gf = c[1][r];
                float gg = c[2][r];
                float go = c[3][r];
                if (LAYER == 0) {
                    gi += breg[0][cc];
                    gf += breg[1][cc];
                    gg += breg[2][cc];
                    go += breg[3][cc];
                } else {
                    gi += GxS[row * 128 + colp + cc];
                    gf += GxS[row * 128 + 32 + colp + cc];
                    gg += GxS[row * 128 + 64 + colp + cc];
                    go += GxS[row * 128 + 96 + colp + cc];
                }
                float ccv = sig_hw(gf) * cstate[e] + sig_hw(gi) * tanh_hw(gg);
                cstate[e] = ccv;
                hv[cc] = sig_hw(go) * tanh_hw(ccv);
            }
            __half2 h2 = __floats2half2_rn(hv[0], hv[1]);
            *(__half2*)&hnh[(size_t)b * HH + n0 + colp] = h2;
            if (LAYER == 0)
                *(__half2*)&g_x1h[((size_t)b * TT + tt) * IN1 + dir * HH + n0 + colp] = h2;
        }
        group_sync(barr, bgen);
    }
}

// ======================= layer-1 input pre-GEMM: fp16 single-pass, occ 2 ======
#define PG_PAD    40
#define PG_HBYTES (128 * PG_PAD * 2)               // 10240 per plane
#define PG_STAGE  (2 * PG_HBYTES)                  // 20480 (Ah, Wh)
#define PG_SMEM   (2 * PG_STAGE)                   // 40960

__device__ __forceinline__ void pg_load_stage(
    uint32_t sbase, const __half* Ah, const __half* Wh, int k0, int tid)
{
#pragma unroll
    for (int i = 0; i < 2; i++) {
        int chunk = tid + 256 * i;
        int row = chunk >> 2, seg = chunk & 3;
        uint32_t doff = (uint32_t)(row * (PG_PAD * 2) + seg * 16);
        CP_ASYNC16(sbase + doff,             (const char*)(Ah + (size_t)row * IN1 + k0) + seg * 16);
        CP_ASYNC16(sbase + PG_HBYTES + doff, (const char*)(Wh + (size_t)row * IN1 + k0) + seg * 16);
    }
}

__global__ void __launch_bounds__(256, 2) pregemm_mma(
    const float* __restrict__ b1f, const float* __restrict__ b1b)
{
    extern __shared__ char smem[];
    __shared__ float bias_s[128];
    const uint32_t s0 = smem_u32(smem);
    const int tid = threadIdx.x;
    const int wid = tid >> 5, lid = tid & 31;
    const int warp_m = wid >> 2, warp_n = wid & 3;

    const int dir   = blockIdx.x >> 3;
    const int ntile = blockIdx.x & 7;
    const int mtile = blockIdx.y;

    const float* bsrc = dir ? b1b : b1f;
    if (tid < 128) bias_s[tid] = bsrc[ntile * 128 + tid];

    const __half* Ah = g_x1h + (size_t)mtile * 128 * IN1;
    const __half* Wh = &g_w1[dir][ntile * 128][0];

    float c[4][4][4];
#pragma unroll
    for (int mt = 0; mt < 4; mt++)
#pragma unroll
        for (int nt = 0; nt < 4; nt++)
#pragma unroll
            for (int r = 0; r < 4; r++) c[mt][nt][r] = 0.f;

    pg_load_stage(s0,            Ah, Wh, 0,  tid); CP_COMMIT();
    pg_load_stage(s0 + PG_STAGE, Ah, Wh, 32, tid); CP_COMMIT();

    const int a_row = (lid & 15);
    const int a_kof = (lid >> 4) * 8;
    const int b_g   = lid >> 3;
    const int b_row = (b_g >> 1) * 8 + (lid & 7);
    const int b_kof = (b_g & 1) * 8;

    for (int ci = 0; ci < 16; ci++) {
        if (ci == 15) CP_WAIT0(); else CP_WAIT1();
        __syncthreads();

        const uint32_t sb = s0 + (ci & 1) * PG_STAGE;
        const uint32_t sA = sb;
        const uint32_t sW = sb + PG_HBYTES;

#pragma unroll
        for (int ks = 0; ks < 32; ks += 16) {
            uint32_t aH[4][4], bW[2][4];
#pragma unroll
            for (int mt = 0; mt < 4; mt++) {
                int row = warp_m * 64 + mt * 16 + a_row;
                uint32_t off = (uint32_t)(row * (PG_PAD * 2) + (ks + a_kof) * 2);
                LDMATRIX_X4(aH[mt][0], aH[mt][1], aH[mt][2], aH[mt][3], sA + off);
            }
#pragma unroll
            for (int bt = 0; bt < 2; bt++) {
                int row = warp_n * 32 + bt * 16 + b_row;
                uint32_t off = (uint32_t)(row * (PG_PAD * 2) + (ks + b_kof) * 2);
                LDMATRIX_X4(bW[bt][0], bW[bt][1], bW[bt][2], bW[bt][3], sW + off);
            }
#pragma unroll
            for (int mt = 0; mt < 4; mt++)
#pragma unroll
                for (int nt = 0; nt < 4; nt++) {
                    int bt = nt >> 1, sub = (nt & 1) * 2;
                    MMA_F16(c[mt][nt][0], c[mt][nt][1], c[mt][nt][2], c[mt][nt][3],
                            aH[mt][0], aH[mt][1], aH[mt][2], aH[mt][3],
                            bW[bt][sub], bW[bt][sub + 1]);
                }
        }
        __syncthreads();
        if (ci + 2 < 16) {
            pg_load_stage(s0 + (ci & 1) * PG_STAGE, Ah, Wh, (ci + 2) * 32, tid);
            CP_COMMIT();
        }
    }

#pragma unroll
    for (int mt = 0; mt < 4; mt++) {
#pragma unroll
        for (int rh = 0; rh < 2; rh++) {
            int row = warp_m * 64 + mt * 16 + (lid >> 2) + rh * 8;
            size_t R = (size_t)mtile * 128 + row;
            int b = (int)(R >> 9), t = (int)(R & 511);
            float* dst = g_gx1 + (((size_t)dir * TT + t) * BB + b) * NG + ntile * 128;
#pragma unroll
            for (int nt = 0; nt < 4; nt++) {
                int col = warp_n * 32 + nt * 8 + (lid & 3) * 2;
                float2 v;
                v.x = c[mt][nt][rh * 2 + 0] + bias_s[col];
                v.y = c[mt][nt][rh * 2 + 1] + bias_s[col + 1];
                *(float2*)(dst + col) = v;
            }
        }
    }
}

// ======================= final projection =======================
__global__ void fc_kernel(const float* __restrict__ fcw, const float* __restrict__ fcb,
                          float* __restrict__ out)
{
    int b = blockIdx.x;
    int l = threadIdx.x;   // 64 threads
    __shared__ float hs[2 * HH];
    for (int j = threadIdx.x; j < 2 * HH; j += blockDim.x) {
        int d = j >> 8, jj = j & 255;
        hs[j] = __half2float(g_hh[1][0][d][b][jj]);
    }
    __syncthreads();
    float s = fcb[l];
#pragma unroll 8
    for (int j = 0; j < 2 * HH; j++)
        s = fmaf(hs[j], fcw[l * (2 * HH) + j], s);
    out[b * LOUT + l] = s;
}

// ---------------- launch ----------------
extern "C" void kernel_launch(void* const* d_in, const int* in_sizes, int n_in,
                              void* d_out, int out_size)
{
    const float* x     = (const float*)d_in[0];
    const float* wih0f = (const float*)d_in[1];
    const float* whh0f = (const float*)d_in[2];
    const float* b0f   = (const float*)d_in[3];
    const float* wih0b = (const float*)d_in[4];
    const float* whh0b = (const float*)d_in[5];
    const float* b0b   = (const float*)d_in[6];
    const float* wih1f = (const float*)d_in[7];
    const float* whh1f = (const float*)d_in[8];
    const float* b1f   = (const float*)d_in[9];
    const float* wih1b = (const float*)d_in[10];
    const float* whh1b = (const float*)d_in[11];
    const float* b1b   = (const float*)d_in[12];
    const float* fcw   = (const float*)d_in[13];
    const float* fcb   = (const float*)d_in[14];
    float* out = (float*)d_out;

    const int SM0 = 160 * ((IN0 + HH + 8) * 2);              // 89600
    const int SM1 = 160 * ((HH + 8) * 2) + 32 * 128 * 4;     // 84480 + 16384 = 100864
    cudaFuncSetAttribute(lstm_seq_tc<16>, cudaFuncAttributeMaxDynamicSharedMemorySize, SM0);
    cudaFuncSetAttribute(lstm_seq_tc<0>,  cudaFuncAttributeMaxDynamicSharedMemorySize, SM1);
    cudaFuncSetAttribute(pregemm_mma, cudaFuncAttributeMaxDynamicSharedMemorySize, PG_SMEM);

    void *a_x0h, *a_w0, *a_whh, *a_w1;
    cudaGetSymbolAddress(&a_x0h, g_x0h);
    cudaGetSymbolAddress(&a_w0, g_w0);
    cudaGetSymbolAddress(&a_whh, g_whh);
    cudaGetSymbolAddress(&a_w1, g_w1);
    __half* p_x0h = (__half*)a_x0h;
    __half* p_w0  = (__half*)a_w0;
    __half* p_whh = (__half*)a_whh;
    __half* p_w1  = (__half*)a_w1;

    zero_kernel<<<128, 256>>>();
    convh_kernel<<<512, 256>>>(x, p_x0h, BB * TT * IN0);
    convh_kernel<<<32, 256>>>(wih0f, p_w0, NG * IN0);
    convh_kernel<<<32, 256>>>(wih0b, p_w0 + NG * IN0, NG * IN0);
    convh_kernel<<<256, 256>>>(whh0f, p_whh + 0 * NG * HH, NG * HH);
    convh_kernel<<<256, 256>>>(whh0b, p_whh + 1 * NG * HH, NG * HH);
    convh_kernel<<<256, 256>>>(whh1f, p_whh + 2 * NG * HH, NG * HH);
    convh_kernel<<<256, 256>>>(whh1b, p_whh + 3 * NG * HH, NG * HH);
    convh_kernel<<<512, 256>>>(wih1f, p_w1, NG * IN1);
    convh_kernel<<<512, 256>>>(wih1b, p_w1 + NG * IN1, NG * IN1);

    lstm_seq_tc<16><<<256, 256, SM0>>>(b0f, b0b);

    dim3 gt(16, 2048, 1);
    pregemm_mma<<<gt, 256, PG_SMEM>>>(b1f, b1b);

    lstm_seq_tc<0><<<256, 256, SM1>>>(nullptr, nullptr);

    fc_kernel<<<BB, LOUT>>>(fcw, fcb, out);
}